// round 1
// baseline (speedup 1.0000x reference)
#include <cuda_runtime.h>
#include <math.h>

#define N_STATIONS 100000
#define N_TIME     1000
#define K_NEIGH    8
#define SMOOTH_C   0.2f
#define KEEP_C     0.8f
#define N_COMP     4
#define COEFF_STRIDE 12   // off, trend, A0..A3, B0..B3, pad, pad
#define TABLE_STRIDE 12   // t, s0..s3, c0..c3, pad, pad, pad
#define CHUNKS     250    // 1000 times / 4 per float4
#define SPB        64     // stations per block in main kernel

// Scratch (no cudaMalloc allowed)
__device__ float g_coeff[N_STATIONS * COEFF_STRIDE];
__device__ float g_table[N_TIME * TABLE_STRIDE];

// ---------------------------------------------------------------------------
// Kernel 1: neighbor smoothing -> per-station coefficients
//   A_i = amp_s * cos(ph_s)   (multiplies sin(w t))
//   B_i = amp_s * sin(ph_s)   (multiplies cos(w t))
// where cos(ph_s) = mix_re / r, sin(ph_s) = mix_im / r  (no atan2 needed)
// ---------------------------------------------------------------------------
__global__ void smooth_kernel(const float* __restrict__ off,
                              const float* __restrict__ trend,
                              const float* __restrict__ amps,
                              const float* __restrict__ phases,
                              const int*   __restrict__ nidx,
                              const float* __restrict__ nw)
{
    int st = blockIdx.x * blockDim.x + threadIdx.x;
    if (st >= N_STATIONS) return;

    float avg_amp[N_COMP] = {0.f, 0.f, 0.f, 0.f};
    float avg_re [N_COMP] = {0.f, 0.f, 0.f, 0.f};
    float avg_im [N_COMP] = {0.f, 0.f, 0.f, 0.f};

#pragma unroll
    for (int k = 0; k < K_NEIGH; ++k) {
        int   nb = nidx[st * K_NEIGH + k];
        float w  = nw  [st * K_NEIGH + k];
        const float4 na = *reinterpret_cast<const float4*>(amps   + nb * 4);
        const float4 np = *reinterpret_cast<const float4*>(phases + nb * 4);
        float av[4] = {na.x, na.y, na.z, na.w};
        float pv[4] = {np.x, np.y, np.z, np.w};
#pragma unroll
        for (int i = 0; i < N_COMP; ++i) {
            avg_amp[i] = fmaf(w, av[i], avg_amp[i]);
            float sp, cp;
            __sincosf(pv[i], &sp, &cp);
            avg_re[i] = fmaf(w, cp, avg_re[i]);
            avg_im[i] = fmaf(w, sp, avg_im[i]);
        }
    }

    const float4 oa = *reinterpret_cast<const float4*>(amps   + st * 4);
    const float4 op = *reinterpret_cast<const float4*>(phases + st * 4);
    float a0[4] = {oa.x, oa.y, oa.z, oa.w};
    float p0[4] = {op.x, op.y, op.z, op.w};

    float c[COEFF_STRIDE];
    c[0] = off[st];
    c[1] = trend[st];
#pragma unroll
    for (int i = 0; i < N_COMP; ++i) {
        float amp_s = KEEP_C * a0[i] + SMOOTH_C * avg_amp[i];
        float sp, cp;
        __sincosf(p0[i], &sp, &cp);
        float mr = KEEP_C * cp + SMOOTH_C * avg_re[i];
        float mi = KEEP_C * sp + SMOOTH_C * avg_im[i];
        float inv = rsqrtf(fmaxf(mr * mr + mi * mi, 1e-30f));
        c[2 + i] = amp_s * mr * inv;   // A_i (x sin(wt))
        c[6 + i] = amp_s * mi * inv;   // B_i (x cos(wt))
    }
    c[10] = 0.f; c[11] = 0.f;

    float4* dst = reinterpret_cast<float4*>(g_coeff + st * COEFF_STRIDE);
    dst[0] = make_float4(c[0], c[1], c[2],  c[3]);
    dst[1] = make_float4(c[4], c[5], c[6],  c[7]);
    dst[2] = make_float4(c[8], c[9], c[10], c[11]);
}

// ---------------------------------------------------------------------------
// Kernel 2: time table: t, sin(w_i t), cos(w_i t) per timestep (accurate)
// ---------------------------------------------------------------------------
__global__ void table_kernel(const float* __restrict__ time_vector,
                             const float* __restrict__ periods)
{
    int j = blockIdx.x * blockDim.x + threadIdx.x;
    if (j >= N_TIME) return;
    float t = time_vector[j];
    float e[TABLE_STRIDE];
    e[0] = t;
#pragma unroll
    for (int i = 0; i < N_COMP; ++i) {
        float freq = 1.0f / periods[i];
        float w = 6.2831853071795864769f * freq;
        float sv, cv;
        sincosf(w * t, &sv, &cv);   // precise: args up to ~126 rad
        e[1 + i] = sv;
        e[5 + i] = cv;
    }
    e[9] = 0.f; e[10] = 0.f; e[11] = 0.f;
    float4* dst = reinterpret_cast<float4*>(g_table + j * TABLE_STRIDE);
    dst[0] = make_float4(e[0], e[1], e[2],  e[3]);
    dst[1] = make_float4(e[4], e[5], e[6],  e[7]);
    dst[2] = make_float4(e[8], e[9], e[10], e[11]);
}

// ---------------------------------------------------------------------------
// Kernel 3: main evaluation. Each thread owns one float4 time-chunk (column),
// table values live in registers, loops over SPB stations. Station coeffs are
// warp-uniform LDGs (L1 broadcast). 9 FFMA / element. float4 coalesced stores.
// ---------------------------------------------------------------------------
__global__ void __launch_bounds__(256) eval_kernel(float* __restrict__ out)
{
    const int col    = threadIdx.x;        // 0..255 ; chunks 0..249 are real
    const bool active = (col < CHUNKS);

    float tt[4];
    float ss[4][4];   // ss[q][i] = sin(w_i * t_{4*col+q})
    float cc[4][4];

    if (active) {
#pragma unroll
        for (int q = 0; q < 4; ++q) {
            const float4* tp = reinterpret_cast<const float4*>(
                g_table + (col * 4 + q) * TABLE_STRIDE);
            float4 a = tp[0];
            float4 b = tp[1];
            float4 d = tp[2];
            tt[q]    = a.x;
            ss[q][0] = a.y; ss[q][1] = a.z; ss[q][2] = a.w; ss[q][3] = b.x;
            cc[q][0] = b.y; cc[q][1] = b.z; cc[q][2] = b.w; cc[q][3] = d.x;
        }
    }

    int s0 = blockIdx.x * SPB;
    int s1 = min(s0 + SPB, N_STATIONS);

    for (int st = s0; st < s1; ++st) {
        const float4* cp = reinterpret_cast<const float4*>(g_coeff + st * COEFF_STRIDE);
        float4 k0 = cp[0];   // off, trend, A0, A1
        float4 k1 = cp[1];   // A2, A3, B0, B1
        float4 k2 = cp[2];   // B2, B3, -, -
        if (active) {
            float v[4];
#pragma unroll
            for (int q = 0; q < 4; ++q) {
                float r = fmaf(k0.y, tt[q], k0.x);
                r = fmaf(k0.z, ss[q][0], r);
                r = fmaf(k0.w, ss[q][1], r);
                r = fmaf(k1.x, ss[q][2], r);
                r = fmaf(k1.y, ss[q][3], r);
                r = fmaf(k1.z, cc[q][0], r);
                r = fmaf(k1.w, cc[q][1], r);
                r = fmaf(k2.x, cc[q][2], r);
                r = fmaf(k2.y, cc[q][3], r);
                v[q] = r;
            }
            float4* optr = reinterpret_cast<float4*>(out + (size_t)st * N_TIME + col * 4);
            *optr = make_float4(v[0], v[1], v[2], v[3]);
        }
    }
}

// ---------------------------------------------------------------------------
extern "C" void kernel_launch(void* const* d_in, const int* in_sizes, int n_in,
                              void* d_out, int out_size)
{
    const float* time_vector = (const float*)d_in[0];
    const float* off         = (const float*)d_in[1];
    const float* trend       = (const float*)d_in[2];
    const float* amps        = (const float*)d_in[3];
    const float* phases      = (const float*)d_in[4];
    const int*   nidx        = (const int*)  d_in[5];
    const float* nw          = (const float*)d_in[6];
    const float* periods     = (const float*)d_in[7];
    float* out = (float*)d_out;

    smooth_kernel<<<(N_STATIONS + 255) / 256, 256>>>(off, trend, amps, phases, nidx, nw);
    table_kernel<<<(N_TIME + 255) / 256, 256>>>(time_vector, periods);
    eval_kernel<<<(N_STATIONS + SPB - 1) / SPB, 256>>>(out);
}